// round 1
// baseline (speedup 1.0000x reference)
#include <cuda_runtime.h>
#include <cuda_bf16.h>
#include <math.h>

// Problem constants
#define NTOK 2048
#define CDIM 768
#define EDIM 8
#define HDIM 3072
#define CAP  2048   // max tokens a single expert can receive (each token -> <=1 slot per expert)

// ---------------- scratch (static device memory; no allocations) ----------------
__device__ float g_xbuf[(size_t)EDIM * CAP * CDIM];   // gathered activations per expert  (48 MB)
__device__ float g_u   [(size_t)EDIM * CAP * HDIM];   // h * silu(g) intermediate        (192 MB)
__device__ float g_o   [(size_t)EDIM * CAP * CDIM];   // proj output per (expert,slot)    (48 MB)
__device__ int   g_cnt [EDIM];                        // tokens per expert
__device__ float g_prob[EDIM * CAP];                  // routing prob per (expert,slot)
__device__ int   g_pidx[2 * NTOK];                    // token -> (e*CAP+slot) x2

// ---------------- helpers ----------------
__device__ __forceinline__ float to_tf32(float x) {
    unsigned u;
    asm("cvt.rna.tf32.f32 %0, %1;" : "=r"(u) : "f"(x));
    return __uint_as_float(u);
}

__device__ __forceinline__ void mma_tf32(float c[4], const unsigned a[4], const unsigned b[2]) {
    asm volatile(
        "mma.sync.aligned.m16n8k8.row.col.f32.tf32.tf32.f32 "
        "{%0,%1,%2,%3},{%4,%5,%6,%7},{%8,%9},{%0,%1,%2,%3};\n"
        : "+f"(c[0]), "+f"(c[1]), "+f"(c[2]), "+f"(c[3])
        : "r"(a[0]), "r"(a[1]), "r"(a[2]), "r"(a[3]), "r"(b[0]), "r"(b[1]));
}

// ---------------- kernel 0: init counters ----------------
__global__ void init_kernel() {
    if (threadIdx.x < EDIM) g_cnt[threadIdx.x] = 0;
}

// ---------------- kernel 1: router + dispatch/gather ----------------
// 1 warp per token; 8 warps per block.
__global__ __launch_bounds__(256) void router_kernel(const float* __restrict__ x,
                                                     const float* __restrict__ wr) {
    const int t = blockIdx.x * 8 + (threadIdx.x >> 5);
    if (t >= NTOK) return;
    const int lane = threadIdx.x & 31;
    const float* xr = x + (size_t)t * CDIM;

    float acc[EDIM];
#pragma unroll
    for (int e = 0; e < EDIM; e++) acc[e] = 0.f;

#pragma unroll
    for (int j = 0; j < CDIM / 32; j++) {
        int i = lane + 32 * j;
        float xv = xr[i];
        const float4* w4 = reinterpret_cast<const float4*>(wr + (size_t)i * EDIM);
        float4 w0 = w4[0], w1 = w4[1];
        acc[0] += xv * w0.x; acc[1] += xv * w0.y; acc[2] += xv * w0.z; acc[3] += xv * w0.w;
        acc[4] += xv * w1.x; acc[5] += xv * w1.y; acc[6] += xv * w1.z; acc[7] += xv * w1.w;
    }
#pragma unroll
    for (int off = 16; off > 0; off >>= 1) {
#pragma unroll
        for (int e = 0; e < EDIM; e++) acc[e] += __shfl_xor_sync(0xffffffffu, acc[e], off);
    }
    // all lanes now hold identical logits
    int e0 = 0; float l0 = acc[0];
#pragma unroll
    for (int e = 1; e < EDIM; e++) if (acc[e] > l0) { l0 = acc[e]; e0 = e; }
    int e1 = -1; float l1 = -INFINITY;
#pragma unroll
    for (int e = 0; e < EDIM; e++) if (e != e0 && acc[e] > l1) { l1 = acc[e]; e1 = e; }

    float ex = expf(l1 - l0);          // <= 1
    float p0 = 1.f / (1.f + ex);
    float p1 = ex * p0;

    int s0 = 0, s1 = 0;
    if (lane == 0) {
        s0 = atomicAdd(&g_cnt[e0], 1);
        s1 = atomicAdd(&g_cnt[e1], 1);
        g_prob[e0 * CAP + s0] = p0;
        g_prob[e1 * CAP + s1] = p1;
        g_pidx[2 * t + 0] = e0 * CAP + s0;
        g_pidx[2 * t + 1] = e1 * CAP + s1;
    }
    s0 = __shfl_sync(0xffffffffu, s0, 0);
    s1 = __shfl_sync(0xffffffffu, s1, 0);

    float* d0 = g_xbuf + ((size_t)e0 * CAP + s0) * CDIM;
    float* d1 = g_xbuf + ((size_t)e1 * CAP + s1) * CDIM;
#pragma unroll
    for (int j = 0; j < CDIM / 32; j++) {
        int i = lane + 32 * j;
        float v = xr[i];
        d0[i] = v;
        d1[i] = v;
    }
}

// ---------------- kernel 2: fused fc + gate GEMM + SwiGLU ----------------
// Block tile 128x64, BK=16, 256 threads (8 warps in 4x2), warp tile 32x32.
// Computes both h = A@Wfc + bfc and g = A@Wg + bg for the same tile,
// stores u = h * silu(g).
__global__ __launch_bounds__(256) void gemm1_kernel(const float* __restrict__ wfc,
                                                    const float* __restrict__ bfc,
                                                    const float* __restrict__ wgt,
                                                    const float* __restrict__ bgt) {
    const int e   = blockIdx.z;
    const int cnt = g_cnt[e];
    const int m0  = blockIdx.y * 128;
    if (m0 >= cnt) return;
    const int n0  = blockIdx.x * 64;

    __shared__ float As[128 * 20];       // stride 20: conflict-free fragment loads
    __shared__ float Bs[2][16 * 72];     // stride 72: conflict-free fragment loads

    const float* Ag = g_xbuf + (size_t)e * CAP * CDIM;
    const float* B0 = wfc + (size_t)e * CDIM * HDIM;
    const float* B1 = wgt + (size_t)e * CDIM * HDIM;

    const int tid = threadIdx.x, lane = tid & 31, wid = tid >> 5;
    const int wm = (wid & 3) * 32, wn = (wid >> 2) * 32;
    const int gq = lane >> 2, tg = lane & 3;

    float cf[2][4][4] = {};
    float cg[2][4][4] = {};

#pragma unroll 1
    for (int k0 = 0; k0 < CDIM; k0 += 16) {
        // A tile: 128x16
#pragma unroll
        for (int i = 0; i < 2; i++) {
            int v = tid * 2 + i, row = v >> 2, kk = (v & 3) * 4;
            float4 a = make_float4(0.f, 0.f, 0.f, 0.f);
            if (m0 + row < cnt)
                a = *(const float4*)(Ag + (size_t)(m0 + row) * CDIM + k0 + kk);
            float* s = As + row * 20 + kk;
            s[0] = to_tf32(a.x); s[1] = to_tf32(a.y); s[2] = to_tf32(a.z); s[3] = to_tf32(a.w);
        }
        // B tiles: 16x64 each
        {
            int kr = tid >> 4, nn = (tid & 15) * 4;
            size_t off = (size_t)(k0 + kr) * HDIM + n0 + nn;
            float4 b = *(const float4*)(B0 + off);
            float* s = &Bs[0][kr * 72 + nn];
            s[0] = to_tf32(b.x); s[1] = to_tf32(b.y); s[2] = to_tf32(b.z); s[3] = to_tf32(b.w);
            float4 c = *(const float4*)(B1 + off);
            float* s2 = &Bs[1][kr * 72 + nn];
            s2[0] = to_tf32(c.x); s2[1] = to_tf32(c.y); s2[2] = to_tf32(c.z); s2[3] = to_tf32(c.w);
        }
        __syncthreads();
#pragma unroll
        for (int ks = 0; ks < 2; ks++) {
            const int kb = ks * 8;
            unsigned af[2][4];
#pragma unroll
            for (int mt = 0; mt < 2; mt++) {
                int r = wm + mt * 16 + gq;
                af[mt][0] = __float_as_uint(As[r * 20 + kb + tg]);
                af[mt][1] = __float_as_uint(As[(r + 8) * 20 + kb + tg]);
                af[mt][2] = __float_as_uint(As[r * 20 + kb + tg + 4]);
                af[mt][3] = __float_as_uint(As[(r + 8) * 20 + kb + tg + 4]);
            }
            unsigned bF[4][2], bG[4][2];
#pragma unroll
            for (int nt = 0; nt < 4; nt++) {
                int cc = wn + nt * 8 + gq;
                bF[nt][0] = __float_as_uint(Bs[0][(kb + tg) * 72 + cc]);
                bF[nt][1] = __float_as_uint(Bs[0][(kb + tg + 4) * 72 + cc]);
                bG[nt][0] = __float_as_uint(Bs[1][(kb + tg) * 72 + cc]);
                bG[nt][1] = __float_as_uint(Bs[1][(kb + tg + 4) * 72 + cc]);
            }
#pragma unroll
            for (int mt = 0; mt < 2; mt++)
#pragma unroll
                for (int nt = 0; nt < 4; nt++) {
                    mma_tf32(cf[mt][nt], af[mt], bF[nt]);
                    mma_tf32(cg[mt][nt], af[mt], bG[nt]);
                }
        }
        __syncthreads();
    }

    // epilogue: u = (h+bfc) * silu(g+bg)
    float* U = g_u + (size_t)e * CAP * HDIM;
#pragma unroll
    for (int mt = 0; mt < 2; mt++) {
#pragma unroll
        for (int nt = 0; nt < 4; nt++) {
            int col = n0 + wn + nt * 8 + tg * 2;
            float bf0 = bfc[(size_t)e * HDIM + col], bf1 = bfc[(size_t)e * HDIM + col + 1];
            float bg0 = bgt[(size_t)e * HDIM + col], bg1 = bgt[(size_t)e * HDIM + col + 1];
            int r0 = m0 + wm + mt * 16 + gq;
            if (r0 < cnt) {
                float h0 = cf[mt][nt][0] + bf0, h1 = cf[mt][nt][1] + bf1;
                float q0 = cg[mt][nt][0] + bg0, q1 = cg[mt][nt][1] + bg1;
                float2 u;
                u.x = h0 * (q0 / (1.f + expf(-q0)));
                u.y = h1 * (q1 / (1.f + expf(-q1)));
                *(float2*)(U + (size_t)r0 * HDIM + col) = u;
            }
            int r1 = r0 + 8;
            if (r1 < cnt) {
                float h0 = cf[mt][nt][2] + bf0, h1 = cf[mt][nt][3] + bf1;
                float q0 = cg[mt][nt][2] + bg0, q1 = cg[mt][nt][3] + bg1;
                float2 u;
                u.x = h0 * (q0 / (1.f + expf(-q0)));
                u.y = h1 * (q1 / (1.f + expf(-q1)));
                *(float2*)(U + (size_t)r1 * HDIM + col) = u;
            }
        }
    }
}

// ---------------- kernel 3: proj GEMM ----------------
// Block tile 128x64, BK=16, K=HDIM. Output: g_o = u @ Wproj + bproj (per (e,slot)).
__global__ __launch_bounds__(256) void gemm2_kernel(const float* __restrict__ wpr,
                                                    const float* __restrict__ bpr) {
    const int e   = blockIdx.z;
    const int cnt = g_cnt[e];
    const int m0  = blockIdx.y * 128;
    if (m0 >= cnt) return;
    const int n0  = blockIdx.x * 64;

    __shared__ float As[128 * 20];
    __shared__ float Bs[16 * 72];

    const float* Ag = g_u + (size_t)e * CAP * HDIM;
    const float* Bp = wpr + (size_t)e * HDIM * CDIM;

    const int tid = threadIdx.x, lane = tid & 31, wid = tid >> 5;
    const int wm = (wid & 3) * 32, wn = (wid >> 2) * 32;
    const int gq = lane >> 2, tg = lane & 3;

    float cc_[2][4][4] = {};

#pragma unroll 1
    for (int k0 = 0; k0 < HDIM; k0 += 16) {
#pragma unroll
        for (int i = 0; i < 2; i++) {
            int v = tid * 2 + i, row = v >> 2, kk = (v & 3) * 4;
            float4 a = make_float4(0.f, 0.f, 0.f, 0.f);
            if (m0 + row < cnt)
                a = *(const float4*)(Ag + (size_t)(m0 + row) * HDIM + k0 + kk);
            float* s = As + row * 20 + kk;
            s[0] = to_tf32(a.x); s[1] = to_tf32(a.y); s[2] = to_tf32(a.z); s[3] = to_tf32(a.w);
        }
        {
            int kr = tid >> 4, nn = (tid & 15) * 4;
            float4 b = *(const float4*)(Bp + (size_t)(k0 + kr) * CDIM + n0 + nn);
            float* s = &Bs[kr * 72 + nn];
            s[0] = to_tf32(b.x); s[1] = to_tf32(b.y); s[2] = to_tf32(b.z); s[3] = to_tf32(b.w);
        }
        __syncthreads();
#pragma unroll
        for (int ks = 0; ks < 2; ks++) {
            const int kb = ks * 8;
            unsigned af[2][4];
#pragma unroll
            for (int mt = 0; mt < 2; mt++) {
                int r = wm + mt * 16 + gq;
                af[mt][0] = __float_as_uint(As[r * 20 + kb + tg]);
                af[mt][1] = __float_as_uint(As[(r + 8) * 20 + kb + tg]);
                af[mt][2] = __float_as_uint(As[r * 20 + kb + tg + 4]);
                af[mt][3] = __float_as_uint(As[(r + 8) * 20 + kb + tg + 4]);
            }
            unsigned bF[4][2];
#pragma unroll
            for (int nt = 0; nt < 4; nt++) {
                int cidx = wn + nt * 8 + gq;
                bF[nt][0] = __float_as_uint(Bs[(kb + tg) * 72 + cidx]);
                bF[nt][1] = __float_as_uint(Bs[(kb + tg + 4) * 72 + cidx]);
            }
#pragma unroll
            for (int mt = 0; mt < 2; mt++)
#pragma unroll
                for (int nt = 0; nt < 4; nt++)
                    mma_tf32(cc_[mt][nt], af[mt], bF[nt]);
        }
        __syncthreads();
    }

    float* O = g_o + (size_t)e * CAP * CDIM;
#pragma unroll
    for (int mt = 0; mt < 2; mt++) {
#pragma unroll
        for (int nt = 0; nt < 4; nt++) {
            int col = n0 + wn + nt * 8 + tg * 2;
            float b0 = bpr[(size_t)e * CDIM + col], b1 = bpr[(size_t)e * CDIM + col + 1];
            int r0 = m0 + wm + mt * 16 + gq;
            if (r0 < cnt) {
                float2 o; o.x = cc_[mt][nt][0] + b0; o.y = cc_[mt][nt][1] + b1;
                *(float2*)(O + (size_t)r0 * CDIM + col) = o;
            }
            int r1 = r0 + 8;
            if (r1 < cnt) {
                float2 o; o.x = cc_[mt][nt][2] + b0; o.y = cc_[mt][nt][3] + b1;
                *(float2*)(O + (size_t)r1 * CDIM + col) = o;
            }
        }
    }
}

// ---------------- kernel 4: deterministic combine ----------------
__global__ __launch_bounds__(192) void combine_kernel(float* __restrict__ out) {
    const int t = blockIdx.x;
    const int c4 = threadIdx.x;            // 192 float4 = 768 floats
    const int i0 = g_pidx[2 * t + 0];
    const int i1 = g_pidx[2 * t + 1];
    const float p0 = g_prob[i0];
    const float p1 = g_prob[i1];
    const float4 o0 = reinterpret_cast<const float4*>(g_o + (size_t)i0 * CDIM)[c4];
    const float4 o1 = reinterpret_cast<const float4*>(g_o + (size_t)i1 * CDIM)[c4];
    float4 y;
    y.x = p0 * o0.x + p1 * o1.x;
    y.y = p0 * o0.y + p1 * o1.y;
    y.z = p0 * o0.z + p1 * o1.z;
    y.w = p0 * o0.w + p1 * o1.w;
    reinterpret_cast<float4*>(out + (size_t)t * CDIM)[c4] = y;
}

// ---------------- launch ----------------
extern "C" void kernel_launch(void* const* d_in, const int* in_sizes, int n_in,
                              void* d_out, int out_size) {
    const float* x    = (const float*)d_in[0];   // (2048,1,768)
    const float* wr   = (const float*)d_in[1];   // (768,8)
    const float* wfc  = (const float*)d_in[2];   // (8,768,3072)
    const float* bfc  = (const float*)d_in[3];   // (8,1,3072)
    const float* wgt  = (const float*)d_in[4];   // (8,768,3072)
    const float* bgt  = (const float*)d_in[5];   // (8,1,3072)
    const float* wpr  = (const float*)d_in[6];   // (8,3072,768)
    const float* bpr  = (const float*)d_in[7];   // (8,1,768)
    float* out = (float*)d_out;                  // (2048,768)

    init_kernel<<<1, 32>>>();
    router_kernel<<<NTOK / 8, 256>>>(x, wr);
    gemm1_kernel<<<dim3(HDIM / 64, CAP / 128, EDIM), 256>>>(wfc, bfc, wgt, bgt);
    gemm2_kernel<<<dim3(CDIM / 64, CAP / 128, EDIM), 256>>>(wpr, bpr);
    combine_kernel<<<NTOK, 192>>>(out);
}

// round 2
// speedup vs baseline: 1.3063x; 1.3063x over previous
#include <cuda_runtime.h>
#include <cuda_bf16.h>
#include <math.h>

// Problem constants
#define NTOK 2048
#define CDIM 768
#define EDIM 8
#define HDIM 3072
#define CAP  2048

// ---------------- scratch (static device memory; no allocations) ----------------
__device__ float g_xbuf[(size_t)EDIM * CAP * CDIM];   // gathered activations (48 MB)
__device__ float g_u   [(size_t)EDIM * CAP * HDIM];   // h * silu(g)          (192 MB)
__device__ float g_o   [(size_t)EDIM * CAP * CDIM];   // proj out split 0     (48 MB)
__device__ float g_o2  [(size_t)EDIM * CAP * CDIM];   // proj out split 1     (48 MB)
__device__ int   g_cnt [EDIM];
__device__ float g_prob[EDIM * CAP];
__device__ int   g_pidx[2 * NTOK];

// ---------------- helpers ----------------
__device__ __forceinline__ float to_tf32(float x) {
    unsigned u;
    asm("cvt.rna.tf32.f32 %0, %1;" : "=r"(u) : "f"(x));
    return __uint_as_float(u);
}

__device__ __forceinline__ void mma_tf32(float c[4], const unsigned a[4], const unsigned b[2]) {
    asm volatile(
        "mma.sync.aligned.m16n8k8.row.col.f32.tf32.tf32.f32 "
        "{%0,%1,%2,%3},{%4,%5,%6,%7},{%8,%9},{%0,%1,%2,%3};\n"
        : "+f"(c[0]), "+f"(c[1]), "+f"(c[2]), "+f"(c[3])
        : "r"(a[0]), "r"(a[1]), "r"(a[2]), "r"(a[3]), "r"(b[0]), "r"(b[1]));
}

__device__ __forceinline__ void sts_tf32_4(float* s, float4 v) {
    float4 t;
    t.x = to_tf32(v.x); t.y = to_tf32(v.y); t.z = to_tf32(v.z); t.w = to_tf32(v.w);
    *reinterpret_cast<float4*>(s) = t;
}

// ---------------- kernel 0: init counters ----------------
__global__ void init_kernel() {
    if (threadIdx.x < EDIM) g_cnt[threadIdx.x] = 0;
}

// ---------------- kernel 1: router + dispatch/gather ----------------
__global__ __launch_bounds__(256) void router_kernel(const float* __restrict__ x,
                                                     const float* __restrict__ wr) {
    const int t = blockIdx.x * 8 + (threadIdx.x >> 5);
    if (t >= NTOK) return;
    const int lane = threadIdx.x & 31;
    const float* xr = x + (size_t)t * CDIM;

    float acc[EDIM];
#pragma unroll
    for (int e = 0; e < EDIM; e++) acc[e] = 0.f;

#pragma unroll
    for (int j = 0; j < CDIM / 32; j++) {
        int i = lane + 32 * j;
        float xv = xr[i];
        const float4* w4 = reinterpret_cast<const float4*>(wr + (size_t)i * EDIM);
        float4 w0 = w4[0], w1 = w4[1];
        acc[0] += xv * w0.x; acc[1] += xv * w0.y; acc[2] += xv * w0.z; acc[3] += xv * w0.w;
        acc[4] += xv * w1.x; acc[5] += xv * w1.y; acc[6] += xv * w1.z; acc[7] += xv * w1.w;
    }
#pragma unroll
    for (int off = 16; off > 0; off >>= 1) {
#pragma unroll
        for (int e = 0; e < EDIM; e++) acc[e] += __shfl_xor_sync(0xffffffffu, acc[e], off);
    }
    int e0 = 0; float l0 = acc[0];
#pragma unroll
    for (int e = 1; e < EDIM; e++) if (acc[e] > l0) { l0 = acc[e]; e0 = e; }
    int e1 = -1; float l1 = -INFINITY;
#pragma unroll
    for (int e = 0; e < EDIM; e++) if (e != e0 && acc[e] > l1) { l1 = acc[e]; e1 = e; }

    float ex = expf(l1 - l0);
    float p0 = 1.f / (1.f + ex);
    float p1 = ex * p0;

    int s0 = 0, s1 = 0;
    if (lane == 0) {
        s0 = atomicAdd(&g_cnt[e0], 1);
        s1 = atomicAdd(&g_cnt[e1], 1);
        g_prob[e0 * CAP + s0] = p0;
        g_prob[e1 * CAP + s1] = p1;
        g_pidx[2 * t + 0] = e0 * CAP + s0;
        g_pidx[2 * t + 1] = e1 * CAP + s1;
    }
    s0 = __shfl_sync(0xffffffffu, s0, 0);
    s1 = __shfl_sync(0xffffffffu, s1, 0);

    float* d0 = g_xbuf + ((size_t)e0 * CAP + s0) * CDIM;
    float* d1 = g_xbuf + ((size_t)e1 * CAP + s1) * CDIM;
#pragma unroll
    for (int j = 0; j < CDIM / 32; j++) {
        int i = lane + 32 * j;
        float v = xr[i];
        d0[i] = v;
        d1[i] = v;
    }
}

// ---------------- kernel 2: fused fc + gate GEMM + SwiGLU (double buffered) ----------------
// Block tile 128x64 (x2 matrices), BK=16, 256 threads, 8 warps (4x2), warp tile 32x32 dual.
__global__ __launch_bounds__(256, 2) void gemm1_kernel(const float* __restrict__ wfc,
                                                       const float* __restrict__ bfc,
                                                       const float* __restrict__ wgt,
                                                       const float* __restrict__ bgt) {
    const int e   = blockIdx.z;
    const int cnt = g_cnt[e];
    const int m0  = blockIdx.y * 128;
    if (m0 >= cnt) return;
    const int n0  = blockIdx.x * 64;

    __shared__ float As[2][128 * 20];
    __shared__ float Bs[2][2][16 * 72];

    const float* Ag = g_xbuf + (size_t)e * CAP * CDIM;
    const float* B0 = wfc + (size_t)e * CDIM * HDIM;
    const float* B1 = wgt + (size_t)e * CDIM * HDIM;

    const int tid = threadIdx.x, lane = tid & 31, wid = tid >> 5;
    const int wm = (wid & 3) * 32, wn = (wid >> 2) * 32;
    const int gq = lane >> 2, tg = lane & 3;

    // loader indices
    const int a_row0 = (tid * 2) >> 2;            // rows for the two A float4s
    const int a_row1 = (tid * 2 + 1) >> 2;
    const int a_kk0  = ((tid * 2) & 3) * 4;
    const int a_kk1  = ((tid * 2 + 1) & 3) * 4;
    const int b_kr = tid >> 4, b_nn = (tid & 15) * 4;

    float cf[2][4][4] = {};
    float cg[2][4][4] = {};

    const int NIT = CDIM / 16;  // 48
    float4 a_pf0, a_pf1, bf_pf, bg_pf;

    // prologue: load stage 0
    {
        float4 z = make_float4(0.f, 0.f, 0.f, 0.f);
        a_pf0 = (m0 + a_row0 < cnt) ? *(const float4*)(Ag + (size_t)(m0 + a_row0) * CDIM + a_kk0) : z;
        a_pf1 = (m0 + a_row1 < cnt) ? *(const float4*)(Ag + (size_t)(m0 + a_row1) * CDIM + a_kk1) : z;
        size_t off = (size_t)b_kr * HDIM + n0 + b_nn;
        bf_pf = *(const float4*)(B0 + off);
        bg_pf = *(const float4*)(B1 + off);
        sts_tf32_4(&As[0][a_row0 * 20 + a_kk0], a_pf0);
        sts_tf32_4(&As[0][a_row1 * 20 + a_kk1], a_pf1);
        sts_tf32_4(&Bs[0][0][b_kr * 72 + b_nn], bf_pf);
        sts_tf32_4(&Bs[0][1][b_kr * 72 + b_nn], bg_pf);
    }
    __syncthreads();

#pragma unroll 1
    for (int it = 0; it < NIT; ++it) {
        const int cur = it & 1, nxt = cur ^ 1;
        const int k1 = (it + 1) * 16;
        if (it + 1 < NIT) {
            float4 z = make_float4(0.f, 0.f, 0.f, 0.f);
            a_pf0 = (m0 + a_row0 < cnt) ? *(const float4*)(Ag + (size_t)(m0 + a_row0) * CDIM + k1 + a_kk0) : z;
            a_pf1 = (m0 + a_row1 < cnt) ? *(const float4*)(Ag + (size_t)(m0 + a_row1) * CDIM + k1 + a_kk1) : z;
            size_t off = (size_t)(k1 + b_kr) * HDIM + n0 + b_nn;
            bf_pf = *(const float4*)(B0 + off);
            bg_pf = *(const float4*)(B1 + off);
        }
#pragma unroll
        for (int ks = 0; ks < 2; ks++) {
            const int kb = ks * 8;
            unsigned af[2][4];
#pragma unroll
            for (int mt = 0; mt < 2; mt++) {
                int r = wm + mt * 16 + gq;
                af[mt][0] = __float_as_uint(As[cur][r * 20 + kb + tg]);
                af[mt][1] = __float_as_uint(As[cur][(r + 8) * 20 + kb + tg]);
                af[mt][2] = __float_as_uint(As[cur][r * 20 + kb + tg + 4]);
                af[mt][3] = __float_as_uint(As[cur][(r + 8) * 20 + kb + tg + 4]);
            }
            unsigned bF[4][2], bG[4][2];
#pragma unroll
            for (int nt = 0; nt < 4; nt++) {
                int cc = wn + nt * 8 + gq;
                bF[nt][0] = __float_as_uint(Bs[cur][0][(kb + tg) * 72 + cc]);
                bF[nt][1] = __float_as_uint(Bs[cur][0][(kb + tg + 4) * 72 + cc]);
                bG[nt][0] = __float_as_uint(Bs[cur][1][(kb + tg) * 72 + cc]);
                bG[nt][1] = __float_as_uint(Bs[cur][1][(kb + tg + 4) * 72 + cc]);
            }
#pragma unroll
            for (int mt = 0; mt < 2; mt++)
#pragma unroll
                for (int nt = 0; nt < 4; nt++) {
                    mma_tf32(cf[mt][nt], af[mt], bF[nt]);
                    mma_tf32(cg[mt][nt], af[mt], bG[nt]);
                }
        }
        if (it + 1 < NIT) {
            sts_tf32_4(&As[nxt][a_row0 * 20 + a_kk0], a_pf0);
            sts_tf32_4(&As[nxt][a_row1 * 20 + a_kk1], a_pf1);
            sts_tf32_4(&Bs[nxt][0][b_kr * 72 + b_nn], bf_pf);
            sts_tf32_4(&Bs[nxt][1][b_kr * 72 + b_nn], bg_pf);
        }
        __syncthreads();
    }

    // epilogue: u = (h+bfc) * silu(g+bg)
    float* U = g_u + (size_t)e * CAP * HDIM;
#pragma unroll
    for (int mt = 0; mt < 2; mt++) {
#pragma unroll
        for (int nt = 0; nt < 4; nt++) {
            int col = n0 + wn + nt * 8 + tg * 2;
            float bf0 = bfc[(size_t)e * HDIM + col], bf1 = bfc[(size_t)e * HDIM + col + 1];
            float bg0 = bgt[(size_t)e * HDIM + col], bg1 = bgt[(size_t)e * HDIM + col + 1];
            int r0 = m0 + wm + mt * 16 + gq;
            if (r0 < cnt) {
                float h0 = cf[mt][nt][0] + bf0, h1 = cf[mt][nt][1] + bf1;
                float q0 = cg[mt][nt][0] + bg0, q1 = cg[mt][nt][1] + bg1;
                float2 u;
                u.x = h0 * (q0 / (1.f + expf(-q0)));
                u.y = h1 * (q1 / (1.f + expf(-q1)));
                *(float2*)(U + (size_t)r0 * HDIM + col) = u;
            }
            int r1 = r0 + 8;
            if (r1 < cnt) {
                float h0 = cf[mt][nt][2] + bf0, h1 = cf[mt][nt][3] + bf1;
                float q0 = cg[mt][nt][2] + bg0, q1 = cg[mt][nt][3] + bg1;
                float2 u;
                u.x = h0 * (q0 / (1.f + expf(-q0)));
                u.y = h1 * (q1 / (1.f + expf(-q1)));
                *(float2*)(U + (size_t)r1 * HDIM + col) = u;
            }
        }
    }
}

// ---------------- kernel 3: proj GEMM (128x128, warp 64x32, double buffered, split-K=2) ----------------
#define SPLITK 1536
__global__ __launch_bounds__(256, 2) void gemm2_kernel(const float* __restrict__ wpr,
                                                       const float* __restrict__ bpr) {
    const int e     = blockIdx.z >> 1;
    const int split = blockIdx.z & 1;
    const int cnt   = g_cnt[e];
    const int m0    = blockIdx.y * 128;
    if (m0 >= cnt) return;
    const int n0    = blockIdx.x * 128;
    const int kbase = split * SPLITK;

    __shared__ float As[2][128 * 20];
    __shared__ float Bs[2][16 * 136];

    const float* Ag = g_u + (size_t)e * CAP * HDIM + kbase;
    const float* Bp = wpr + (size_t)e * HDIM * CDIM + (size_t)kbase * CDIM;

    const int tid = threadIdx.x, lane = tid & 31, wid = tid >> 5;
    const int wm = (wid & 1) * 64, wn = (wid >> 1) * 32;
    const int gq = lane >> 2, tg = lane & 3;

    const int a_row0 = (tid * 2) >> 2;
    const int a_row1 = (tid * 2 + 1) >> 2;
    const int a_kk0  = ((tid * 2) & 3) * 4;
    const int a_kk1  = ((tid * 2 + 1) & 3) * 4;
    const int b_kr0 = (tid * 2) >> 5,     b_nn0 = ((tid * 2) & 31) * 4;
    const int b_kr1 = (tid * 2 + 1) >> 5, b_nn1 = ((tid * 2 + 1) & 31) * 4;

    float acc[4][4][4] = {};

    const int NIT = SPLITK / 16;  // 96
    float4 a_pf0, a_pf1, b_pf0, b_pf1;

    {
        float4 z = make_float4(0.f, 0.f, 0.f, 0.f);
        a_pf0 = (m0 + a_row0 < cnt) ? *(const float4*)(Ag + (size_t)(m0 + a_row0) * HDIM + a_kk0) : z;
        a_pf1 = (m0 + a_row1 < cnt) ? *(const float4*)(Ag + (size_t)(m0 + a_row1) * HDIM + a_kk1) : z;
        b_pf0 = *(const float4*)(Bp + (size_t)b_kr0 * CDIM + n0 + b_nn0);
        b_pf1 = *(const float4*)(Bp + (size_t)b_kr1 * CDIM + n0 + b_nn1);
        sts_tf32_4(&As[0][a_row0 * 20 + a_kk0], a_pf0);
        sts_tf32_4(&As[0][a_row1 * 20 + a_kk1], a_pf1);
        sts_tf32_4(&Bs[0][b_kr0 * 136 + b_nn0], b_pf0);
        sts_tf32_4(&Bs[0][b_kr1 * 136 + b_nn1], b_pf1);
    }
    __syncthreads();

#pragma unroll 1
    for (int it = 0; it < NIT; ++it) {
        const int cur = it & 1, nxt = cur ^ 1;
        const int k1 = (it + 1) * 16;
        if (it + 1 < NIT) {
            float4 z = make_float4(0.f, 0.f, 0.f, 0.f);
            a_pf0 = (m0 + a_row0 < cnt) ? *(const float4*)(Ag + (size_t)(m0 + a_row0) * HDIM + k1 + a_kk0) : z;
            a_pf1 = (m0 + a_row1 < cnt) ? *(const float4*)(Ag + (size_t)(m0 + a_row1) * HDIM + k1 + a_kk1) : z;
            b_pf0 = *(const float4*)(Bp + (size_t)(k1 + b_kr0) * CDIM + n0 + b_nn0);
            b_pf1 = *(const float4*)(Bp + (size_t)(k1 + b_kr1) * CDIM + n0 + b_nn1);
        }
#pragma unroll
        for (int ks = 0; ks < 2; ks++) {
            const int kb = ks * 8;
            unsigned af[4][4];
#pragma unroll
            for (int mt = 0; mt < 4; mt++) {
                int r = wm + mt * 16 + gq;
                af[mt][0] = __float_as_uint(As[cur][r * 20 + kb + tg]);
                af[mt][1] = __float_as_uint(As[cur][(r + 8) * 20 + kb + tg]);
                af[mt][2] = __float_as_uint(As[cur][r * 20 + kb + tg + 4]);
                af[mt][3] = __float_as_uint(As[cur][(r + 8) * 20 + kb + tg + 4]);
            }
            unsigned bF[4][2];
#pragma unroll
            for (int nt = 0; nt < 4; nt++) {
                int cc = wn + nt * 8 + gq;
                bF[nt][0] = __float_as_uint(Bs[cur][(kb + tg) * 136 + cc]);
                bF[nt][1] = __float_as_uint(Bs[cur][(kb + tg + 4) * 136 + cc]);
            }
#pragma unroll
            for (int mt = 0; mt < 4; mt++)
#pragma unroll
                for (int nt = 0; nt < 4; nt++)
                    mma_tf32(acc[mt][nt], af[mt], bF[nt]);
        }
        if (it + 1 < NIT) {
            sts_tf32_4(&As[nxt][a_row0 * 20 + a_kk0], a_pf0);
            sts_tf32_4(&As[nxt][a_row1 * 20 + a_kk1], a_pf1);
            sts_tf32_4(&Bs[nxt][b_kr0 * 136 + b_nn0], b_pf0);
            sts_tf32_4(&Bs[nxt][b_kr1 * 136 + b_nn1], b_pf1);
        }
        __syncthreads();
    }

    float* O = (split == 0 ? g_o : g_o2) + (size_t)e * CAP * CDIM;
#pragma unroll
    for (int mt = 0; mt < 4; mt++) {
#pragma unroll
        for (int nt = 0; nt < 4; nt++) {
            int col = n0 + wn + nt * 8 + tg * 2;
            float b0 = 0.f, b1 = 0.f;
            if (split == 0) {
                b0 = bpr[(size_t)e * CDIM + col];
                b1 = bpr[(size_t)e * CDIM + col + 1];
            }
            int r0 = m0 + wm + mt * 16 + gq;
            if (r0 < cnt) {
                float2 o; o.x = acc[mt][nt][0] + b0; o.y = acc[mt][nt][1] + b1;
                *(float2*)(O + (size_t)r0 * CDIM + col) = o;
            }
            int r1 = r0 + 8;
            if (r1 < cnt) {
                float2 o; o.x = acc[mt][nt][2] + b0; o.y = acc[mt][nt][3] + b1;
                *(float2*)(O + (size_t)r1 * CDIM + col) = o;
            }
        }
    }
}

// ---------------- kernel 4: deterministic combine (sums split-K halves) ----------------
__global__ __launch_bounds__(192) void combine_kernel(float* __restrict__ out) {
    const int t = blockIdx.x;
    const int c4 = threadIdx.x;
    const int i0 = g_pidx[2 * t + 0];
    const int i1 = g_pidx[2 * t + 1];
    const float p0 = g_prob[i0];
    const float p1 = g_prob[i1];
    const float4 a0 = reinterpret_cast<const float4*>(g_o  + (size_t)i0 * CDIM)[c4];
    const float4 a1 = reinterpret_cast<const float4*>(g_o2 + (size_t)i0 * CDIM)[c4];
    const float4 b0 = reinterpret_cast<const float4*>(g_o  + (size_t)i1 * CDIM)[c4];
    const float4 b1 = reinterpret_cast<const float4*>(g_o2 + (size_t)i1 * CDIM)[c4];
    float4 y;
    y.x = p0 * (a0.x + a1.x) + p1 * (b0.x + b1.x);
    y.y = p0 * (a0.y + a1.y) + p1 * (b0.y + b1.y);
    y.z = p0 * (a0.z + a1.z) + p1 * (b0.z + b1.z);
    y.w = p0 * (a0.w + a1.w) + p1 * (b0.w + b1.w);
    reinterpret_cast<float4*>(out + (size_t)t * CDIM)[c4] = y;
}

// ---------------- launch ----------------
extern "C" void kernel_launch(void* const* d_in, const int* in_sizes, int n_in,
                              void* d_out, int out_size) {
    const float* x    = (const float*)d_in[0];
    const float* wr   = (const float*)d_in[1];
    const float* wfc  = (const float*)d_in[2];
    const float* bfc  = (const float*)d_in[3];
    const float* wgt  = (const float*)d_in[4];
    const float* bgt  = (const float*)d_in[5];
    const float* wpr  = (const float*)d_in[6];
    const float* bpr  = (const float*)d_in[7];
    float* out = (float*)d_out;

    init_kernel<<<1, 32>>>();
    router_kernel<<<NTOK / 8, 256>>>(x, wr);
    gemm1_kernel<<<dim3(HDIM / 64, CAP / 128, EDIM), 256>>>(wfc, bfc, wgt, bgt);
    gemm2_kernel<<<dim3(CDIM / 128, CAP / 128, EDIM * 2), 256>>>(wpr, bpr);
    combine_kernel<<<NTOK, 192>>>(out);
}

// round 4
// speedup vs baseline: 1.9664x; 1.5053x over previous
#include <cuda_runtime.h>
#include <cuda_bf16.h>
#include <math.h>
#include <stdint.h>

// Problem constants
#define NTOK 2048
#define CDIM 768
#define EDIM 8
#define HDIM 3072
#define CAP  2048

// ---------------- scratch (static device memory; no allocations) ----------------
__device__ float g_xbuf[(size_t)EDIM * CAP * CDIM];   // gathered activations (tf32 RNA-rounded)
__device__ float g_u   [(size_t)EDIM * CAP * HDIM];   // h*silu(g) (tf32 RNA-rounded)
__device__ float g_o   [(size_t)EDIM * CAP * CDIM];   // proj out split 0
__device__ float g_o2  [(size_t)EDIM * CAP * CDIM];   // proj out split 1
__device__ int   g_cnt [EDIM];
__device__ float g_prob[EDIM * CAP];
__device__ int   g_pidx[2 * NTOK];

// ---------------- helpers ----------------
__device__ __forceinline__ float to_tf32(float x) {
    unsigned u;
    asm("cvt.rna.tf32.f32 %0, %1;" : "=r"(u) : "f"(x));
    return __uint_as_float(u);
}

// LDS + RNA-round to tf32, returned as raw bits for mma
__device__ __forceinline__ unsigned lds_tf32(const float* p) {
    return __float_as_uint(to_tf32(*p));
}

__device__ __forceinline__ void mma_tf32(float c[4], const unsigned a[4], const unsigned b[2]) {
    asm volatile(
        "mma.sync.aligned.m16n8k8.row.col.f32.tf32.tf32.f32 "
        "{%0,%1,%2,%3},{%4,%5,%6,%7},{%8,%9},{%0,%1,%2,%3};\n"
        : "+f"(c[0]), "+f"(c[1]), "+f"(c[2]), "+f"(c[3])
        : "r"(a[0]), "r"(a[1]), "r"(a[2]), "r"(a[3]), "r"(b[0]), "r"(b[1]));
}

__device__ __forceinline__ void cpa16(uint32_t dst, const void* src, int sz) {
    asm volatile("cp.async.cg.shared.global [%0], [%1], 16, %2;"
                 :: "r"(dst), "l"(src), "r"(sz));
}
__device__ __forceinline__ void cpa16u(uint32_t dst, const void* src) {
    asm volatile("cp.async.cg.shared.global [%0], [%1], 16;"
                 :: "r"(dst), "l"(src));
}
__device__ __forceinline__ void cpa_commit() { asm volatile("cp.async.commit_group;"); }
__device__ __forceinline__ void cpa_wait1()  { asm volatile("cp.async.wait_group 1;" ::: "memory"); }
__device__ __forceinline__ void cpa_wait0()  { asm volatile("cp.async.wait_group 0;" ::: "memory"); }

__device__ __forceinline__ uint32_t smem_u32(const void* p) {
    return (uint32_t)__cvta_generic_to_shared(p);
}

// ---------------- kernel 0: init counters ----------------
__global__ void init_kernel() {
    if (threadIdx.x < EDIM) g_cnt[threadIdx.x] = 0;
}

// ---------------- kernel 1: router + dispatch/gather (tf32 RNA-rounded gather) ----------------
__global__ __launch_bounds__(256) void router_kernel(const float* __restrict__ x,
                                                     const float* __restrict__ wr) {
    const int t = blockIdx.x * 8 + (threadIdx.x >> 5);
    if (t >= NTOK) return;
    const int lane = threadIdx.x & 31;
    const float* xr = x + (size_t)t * CDIM;

    float acc[EDIM];
#pragma unroll
    for (int e = 0; e < EDIM; e++) acc[e] = 0.f;
#pragma unroll
    for (int j = 0; j < CDIM / 32; j++) {
        int i = lane + 32 * j;
        float xv = xr[i];
        const float4* w4 = reinterpret_cast<const float4*>(wr + (size_t)i * EDIM);
        float4 w0 = w4[0], w1 = w4[1];
        acc[0] += xv * w0.x; acc[1] += xv * w0.y; acc[2] += xv * w0.z; acc[3] += xv * w0.w;
        acc[4] += xv * w1.x; acc[5] += xv * w1.y; acc[6] += xv * w1.z; acc[7] += xv * w1.w;
    }
#pragma unroll
    for (int off = 16; off > 0; off >>= 1) {
#pragma unroll
        for (int e = 0; e < EDIM; e++) acc[e] += __shfl_xor_sync(0xffffffffu, acc[e], off);
    }
    int e0 = 0; float l0 = acc[0];
#pragma unroll
    for (int e = 1; e < EDIM; e++) if (acc[e] > l0) { l0 = acc[e]; e0 = e; }
    int e1 = -1; float l1 = -INFINITY;
#pragma unroll
    for (int e = 0; e < EDIM; e++) if (e != e0 && acc[e] > l1) { l1 = acc[e]; e1 = e; }

    float ex = expf(l1 - l0);
    float p0 = 1.f / (1.f + ex);
    float p1 = ex * p0;

    int s0 = 0, s1 = 0;
    if (lane == 0) {
        s0 = atomicAdd(&g_cnt[e0], 1);
        s1 = atomicAdd(&g_cnt[e1], 1);
        g_prob[e0 * CAP + s0] = p0;
        g_prob[e1 * CAP + s1] = p1;
        g_pidx[2 * t + 0] = e0 * CAP + s0;
        g_pidx[2 * t + 1] = e1 * CAP + s1;
    }
    s0 = __shfl_sync(0xffffffffu, s0, 0);
    s1 = __shfl_sync(0xffffffffu, s1, 0);

    float* d0 = g_xbuf + ((size_t)e0 * CAP + s0) * CDIM;
    float* d1 = g_xbuf + ((size_t)e1 * CAP + s1) * CDIM;
#pragma unroll
    for (int j = 0; j < CDIM / 32; j++) {
        int i = lane + 32 * j;
        float v = to_tf32(xr[i]);
        d0[i] = v;
        d1[i] = v;
    }
}

// ================= GEMM1: fused fc+gate, block 128x64 (x2), BK=32, cp.async 2-stage =================
// smem (floats): As[2][128*36] | Bf[2][32*72] | Bg[2][32*72]  = 73728 bytes
#define G1_SMEM_BYTES 73728
#define G1_AS   4608          // floats per A stage
#define G1_BS   2304          // floats per B stage (each matrix)
#define G1_BF0  (2 * G1_AS)
#define G1_BG0  (G1_BF0 + 2 * G1_BS)

__global__ __launch_bounds__(256, 2) void gemm1_kernel(const float* __restrict__ wfc,
                                                       const float* __restrict__ bfc,
                                                       const float* __restrict__ wgt,
                                                       const float* __restrict__ bgt) {
    extern __shared__ float smem[];
    const int e   = blockIdx.z;
    const int cnt = g_cnt[e];
    const int m0  = blockIdx.y * 128;
    if (m0 >= cnt) return;
    const int n0  = blockIdx.x * 64;

    const float* Ag = g_xbuf + (size_t)e * CAP * CDIM;
    const float* B0 = wfc + (size_t)e * CDIM * HDIM;
    const float* B1 = wgt + (size_t)e * CDIM * HDIM;

    const int tid = threadIdx.x, lane = tid & 31, wid = tid >> 5;
    const int wm = (wid & 3) * 32, wn = (wid >> 2) * 32;
    const int gq = lane >> 2, tg = lane & 3;

    const uint32_t sA  = smem_u32(smem);
    const uint32_t sBf = sA + G1_BF0 * 4;
    const uint32_t sBg = sA + G1_BG0 * 4;

    // A loader: 1024 float4 per stage, 4 per thread: v = tid + 256*i, row=v>>3, c4=v&7
    // B loader (each): 512 float4, 2 per thread: v = tid + 256*i, row=v>>4, c4=v&15
    auto load_stage = [&](int buf, int k0) {
#pragma unroll
        for (int i = 0; i < 4; i++) {
            int v = tid + 256 * i, row = v >> 3, c4 = v & 7;
            int sz = (m0 + row < cnt) ? 16 : 0;
            cpa16(sA + (uint32_t)(buf * G1_AS + row * 36 + c4 * 4) * 4,
                  Ag + (size_t)(m0 + row) * CDIM + k0 + c4 * 4, sz);
        }
#pragma unroll
        for (int i = 0; i < 2; i++) {
            int v = tid + 256 * i, row = v >> 4, c4 = v & 15;
            size_t off = (size_t)(k0 + row) * HDIM + n0 + c4 * 4;
            uint32_t so = (uint32_t)(buf * G1_BS + row * 72 + c4 * 4) * 4;
            cpa16u(sBf + so, B0 + off);
            cpa16u(sBg + so, B1 + off);
        }
        cpa_commit();
    };

    float cf[2][4][4] = {};
    float cg[2][4][4] = {};

    const int NIT = CDIM / 32;  // 24
    load_stage(0, 0);
    load_stage(1, 32);

#pragma unroll 1
    for (int it = 0; it < NIT; ++it) {
        const int cur = it & 1;
        if (it + 1 < NIT) cpa_wait1(); else cpa_wait0();
        __syncthreads();

        const float* As = smem + cur * G1_AS;
        const float* Bf = smem + G1_BF0 + cur * G1_BS;
        const float* Bg = smem + G1_BG0 + cur * G1_BS;
#pragma unroll
        for (int ks = 0; ks < 4; ks++) {
            const int kb = ks * 8;
            unsigned af[2][4];
#pragma unroll
            for (int mt = 0; mt < 2; mt++) {
                int r = wm + mt * 16 + gq;
                af[mt][0] = __float_as_uint(As[r * 36 + kb + tg]);
                af[mt][1] = __float_as_uint(As[(r + 8) * 36 + kb + tg]);
                af[mt][2] = __float_as_uint(As[r * 36 + kb + tg + 4]);
                af[mt][3] = __float_as_uint(As[(r + 8) * 36 + kb + tg + 4]);
            }
            unsigned bF[4][2], bG[4][2];
#pragma unroll
            for (int nt = 0; nt < 4; nt++) {
                int cc = wn + nt * 8 + gq;
                bF[nt][0] = lds_tf32(&Bf[(kb + tg) * 72 + cc]);
                bF[nt][1] = lds_tf32(&Bf[(kb + tg + 4) * 72 + cc]);
                bG[nt][0] = lds_tf32(&Bg[(kb + tg) * 72 + cc]);
                bG[nt][1] = lds_tf32(&Bg[(kb + tg + 4) * 72 + cc]);
            }
#pragma unroll
            for (int mt = 0; mt < 2; mt++)
#pragma unroll
                for (int nt = 0; nt < 4; nt++) {
                    mma_tf32(cf[mt][nt], af[mt], bF[nt]);
                    mma_tf32(cg[mt][nt], af[mt], bG[nt]);
                }
        }
        __syncthreads();
        if (it + 2 < NIT) load_stage(cur, (it + 2) * 32);
    }

    // epilogue: u = (h+bfc) * silu(g+bg), RNA tf32-rounded
    float* U = g_u + (size_t)e * CAP * HDIM;
#pragma unroll
    for (int mt = 0; mt < 2; mt++) {
#pragma unroll
        for (int nt = 0; nt < 4; nt++) {
            int col = n0 + wn + nt * 8 + tg * 2;
            float bf0 = bfc[(size_t)e * HDIM + col], bf1 = bfc[(size_t)e * HDIM + col + 1];
            float bg0 = bgt[(size_t)e * HDIM + col], bg1 = bgt[(size_t)e * HDIM + col + 1];
            int r0 = m0 + wm + mt * 16 + gq;
            if (r0 < cnt) {
                float h0 = cf[mt][nt][0] + bf0, h1 = cf[mt][nt][1] + bf1;
                float q0 = cg[mt][nt][0] + bg0, q1 = cg[mt][nt][1] + bg1;
                float2 u;
                u.x = to_tf32(h0 * (q0 / (1.f + expf(-q0))));
                u.y = to_tf32(h1 * (q1 / (1.f + expf(-q1))));
                *(float2*)(U + (size_t)r0 * HDIM + col) = u;
            }
            int r1 = r0 + 8;
            if (r1 < cnt) {
                float h0 = cf[mt][nt][2] + bf0, h1 = cf[mt][nt][3] + bf1;
                float q0 = cg[mt][nt][2] + bg0, q1 = cg[mt][nt][3] + bg1;
                float2 u;
                u.x = to_tf32(h0 * (q0 / (1.f + expf(-q0))));
                u.y = to_tf32(h1 * (q1 / (1.f + expf(-q1))));
                *(float2*)(U + (size_t)r1 * HDIM + col) = u;
            }
        }
    }
}

// ================= GEMM2: proj, block 128x128, warp 64x32, BK=32, cp.async 2-stage, split-K=2 =================
// smem (floats): As[2][128*36] | Bs[2][32*136]  = 71680 bytes
#define G2_SMEM_BYTES 71680
#define G2_AS 4608
#define G2_BS 4352
#define G2_B0 (2 * G2_AS)
#define SPLITK 1536

__global__ __launch_bounds__(256, 2) void gemm2_kernel(const float* __restrict__ wpr,
                                                       const float* __restrict__ bpr) {
    extern __shared__ float smem[];
    const int e     = blockIdx.z >> 1;
    const int split = blockIdx.z & 1;
    const int cnt   = g_cnt[e];
    const int m0    = blockIdx.y * 128;
    if (m0 >= cnt) return;
    const int n0    = blockIdx.x * 128;
    const int kbase = split * SPLITK;

    const float* Ag = g_u + (size_t)e * CAP * HDIM + kbase;
    const float* Bp = wpr + (size_t)e * HDIM * CDIM + (size_t)kbase * CDIM;

    const int tid = threadIdx.x, lane = tid & 31, wid = tid >> 5;
    const int wm = (wid & 1) * 64, wn = (wid >> 1) * 32;
    const int gq = lane >> 2, tg = lane & 3;

    const uint32_t sA = smem_u32(smem);
    const uint32_t sB = sA + G2_B0 * 4;

    auto load_stage = [&](int buf, int k0) {
#pragma unroll
        for (int i = 0; i < 4; i++) {
            int v = tid + 256 * i, row = v >> 3, c4 = v & 7;
            int sz = (m0 + row < cnt) ? 16 : 0;
            cpa16(sA + (uint32_t)(buf * G2_AS + row * 36 + c4 * 4) * 4,
                  Ag + (size_t)(m0 + row) * HDIM + k0 + c4 * 4, sz);
        }
#pragma unroll
        for (int i = 0; i < 4; i++) {
            int v = tid + 256 * i, row = v >> 5, c4 = v & 31;
            cpa16u(sB + (uint32_t)(buf * G2_BS + row * 136 + c4 * 4) * 4,
                   Bp + (size_t)(k0 + row) * CDIM + n0 + c4 * 4);
        }
        cpa_commit();
    };

    float acc[4][4][4] = {};

    const int NIT = SPLITK / 32;  // 48
    load_stage(0, 0);
    load_stage(1, 32);

#pragma unroll 1
    for (int it = 0; it < NIT; ++it) {
        const int cur = it & 1;
        if (it + 1 < NIT) cpa_wait1(); else cpa_wait0();
        __syncthreads();

        const float* As = smem + cur * G2_AS;
        const float* Bs = smem + G2_B0 + cur * G2_BS;
#pragma unroll
        for (int ks = 0; ks < 4; ks++) {
            const int kb = ks * 8;
            unsigned af[4][4];
#pragma unroll
            for (int mt = 0; mt < 4; mt++) {
                int r = wm + mt * 16 + gq;
                af[mt][0] = __float_as_uint(As[r * 36 + kb + tg]);
                af[mt][1] = __float_as_uint(As[(r + 8) * 36 + kb + tg]);
                af[mt][2] = __float_as_uint(As[r * 36 + kb + tg + 4]);
                af[mt][3] = __float_as_uint(As[(r + 8) * 36 + kb + tg + 4]);
            }
            unsigned bF[4][2];
#pragma unroll
            for (int nt = 0; nt < 4; nt++) {
                int cc = wn + nt * 8 + gq;
                bF[nt][0] = lds_tf32(&Bs[(kb + tg) * 136 + cc]);
                bF[nt][1] = lds_tf32(&Bs[(kb + tg + 4) * 136 + cc]);
            }
#pragma unroll
            for (int mt = 0; mt < 4; mt++)
#pragma unroll
                for (int nt = 0; nt < 4; nt++)
                    mma_tf32(acc[mt][nt], af[mt], bF[nt]);
        }
        __syncthreads();
        if (it + 2 < NIT) load_stage(cur, (it + 2) * 32);
    }

    float* O = (split == 0 ? g_o : g_o2) + (size_t)e * CAP * CDIM;
#pragma unroll
    for (int mt = 0; mt < 4; mt++) {
#pragma unroll
        for (int nt = 0; nt < 4; nt++) {
            int col = n0 + wn + nt * 8 + tg * 2;
            float b0 = 0.f, b1 = 0.f;
            if (split == 0) {
                b0 = bpr[(size_t)e * CDIM + col];
                b1 = bpr[(size_t)e * CDIM + col + 1];
            }
            int r0 = m0 + wm + mt * 16 + gq;
            if (r0 < cnt) {
                float2 o; o.x = acc[mt][nt][0] + b0; o.y = acc[mt][nt][1] + b1;
                *(float2*)(O + (size_t)r0 * CDIM + col) = o;
            }
            int r1 = r0 + 8;
            if (r1 < cnt) {
                float2 o; o.x = acc[mt][nt][2] + b0; o.y = acc[mt][nt][3] + b1;
                *(float2*)(O + (size_t)r1 * CDIM + col) = o;
            }
        }
    }
}

// ---------------- kernel 4: deterministic combine (sums split-K halves) ----------------
__global__ __launch_bounds__(192) void combine_kernel(float* __restrict__ out) {
    const int t = blockIdx.x;
    const int c4 = threadIdx.x;
    const int i0 = g_pidx[2 * t + 0];
    const int i1 = g_pidx[2 * t + 1];
    const float p0 = g_prob[i0];
    const float p1 = g_prob[i1];
    const float4 a0 = reinterpret_cast<const float4*>(g_o  + (size_t)i0 * CDIM)[c4];
    const float4 a1 = reinterpret_cast<const float4*>(g_o2 + (size_t)i0 * CDIM)[c4];
    const float4 b0 = reinterpret_cast<const float4*>(g_o  + (size_t)i1 * CDIM)[c4];
    const float4 b1 = reinterpret_cast<const float4*>(g_o2 + (size_t)i1 * CDIM)[c4];
    float4 y;
    y.x = p0 * (a0.x + a1.x) + p1 * (b0.x + b1.x);
    y.y = p0 * (a0.y + a1.y) + p1 * (b0.y + b1.y);
    y.z = p0 * (a0.z + a1.z) + p1 * (b0.z + b1.z);
    y.w = p0 * (a0.w + a1.w) + p1 * (b0.w + b1.w);
    reinterpret_cast<float4*>(out + (size_t)t * CDIM)[c4] = y;
}

// ---------------- launch ----------------
extern "C" void kernel_launch(void* const* d_in, const int* in_sizes, int n_in,
                              void* d_out, int out_size) {
    const float* x    = (const float*)d_in[0];
    const float* wr   = (const float*)d_in[1];
    const float* wfc  = (const float*)d_in[2];
    const float* bfc  = (const float*)d_in[3];
    const float* wgt  = (const float*)d_in[4];
    const float* bgt  = (const float*)d_in[5];
    const float* wpr  = (const float*)d_in[6];
    const float* bpr  = (const float*)d_in[7];
    float* out = (float*)d_out;

    static bool attr_set = false;
    cudaFuncSetAttribute(gemm1_kernel, cudaFuncAttributeMaxDynamicSharedMemorySize, G1_SMEM_BYTES);
    cudaFuncSetAttribute(gemm2_kernel, cudaFuncAttributeMaxDynamicSharedMemorySize, G2_SMEM_BYTES);
    (void)attr_set;

    init_kernel<<<1, 32>>>();
    router_kernel<<<NTOK / 8, 256>>>(x, wr);
    gemm1_kernel<<<dim3(HDIM / 64, CAP / 128, EDIM), 256, G1_SMEM_BYTES>>>(wfc, bfc, wgt, bgt);
    gemm2_kernel<<<dim3(CDIM / 128, CAP / 128, EDIM * 2), 256, G2_SMEM_BYTES>>>(wpr, bpr);
    combine_kernel<<<NTOK, 192>>>(out);
}